// round 13
// baseline (speedup 1.0000x reference)
#include <cuda_runtime.h>
#include <cuda_fp16.h>
#include <math.h>
#include <stdint.h>

// ---------------------------------------------------------------------------
// MambaBlock: B=2, L=2048, D_MODEL=768, D_INNER=1536, D_STATE=16, DT_RANK=48
// ---------------------------------------------------------------------------
#define BB   2
#define LL   2048
#define DM   768
#define DI   1536
#define NS   16
#define RK   48
#define MROWS (BB * LL)       // 4096
#define XP    80              // DT_RANK + 2*D_STATE
#define SEG   16
#define SLEN  (LL / SEG)      // 128

// ---------------- scratch (device globals; no allocation allowed) ----------
__device__ float g_xz  [MROWS * 2 * DI];   // in_proj output [4096, 3072]
__device__ float g_u   [MROWS * DI];       // conv+silu output
__device__ float g_xdbl[MROWS * XP];       // x_proj output [4096, 80]
__device__ float g_xp  [4 * MROWS * XP];   // x_proj split-K partials
__device__ float g_dt  [MROWS * DI];       // softplus(dt_proj)
__device__ float g_ob  [MROWS * DM];       // out_proj partial 0
__device__ float g_ob2 [MROWS * DM];       // out_proj partial 1
// segmented-scan state
__device__ float g_hend[BB * SEG * DI * NS];
__device__ float g_pend[BB * SEG * DI * NS];
__device__ float g_hin [BB * SEG * DI * NS];
// fp16 staging for tensor GEMMs
__device__ __half g_ah [MROWS * DI];       // A hi
__device__ __half g_al [MROWS * DI];       // A lo
__device__ __half g_bh [2 * DI * DM];      // in_proj_w fp16
__device__ __half g_bh2[DM * DI];          // out_proj_w fp16

// ===========================================================================
// helpers
// ===========================================================================
__device__ __forceinline__ uint32_t smem_u32(const void* p) {
    uint32_t a;
    asm("{ .reg .u64 t; cvta.to.shared.u64 t, %1; cvt.u32.u64 %0, t; }"
        : "=r"(a) : "l"(p));
    return a;
}
__device__ __forceinline__ void ldsm_x4(uint32_t& r0, uint32_t& r1,
                                        uint32_t& r2, uint32_t& r3, uint32_t addr) {
    asm volatile("ldmatrix.sync.aligned.m8n8.x4.shared.b16 {%0,%1,%2,%3}, [%4];"
                 : "=r"(r0), "=r"(r1), "=r"(r2), "=r"(r3) : "r"(addr));
}
__device__ __forceinline__ void mma_f16(float* c, const uint32_t* a,
                                        uint32_t b0, uint32_t b1) {
    asm volatile(
        "mma.sync.aligned.m16n8k16.row.col.f32.f16.f16.f32 "
        "{%0,%1,%2,%3}, {%4,%5,%6,%7}, {%8,%9}, {%0,%1,%2,%3};"
        : "+f"(c[0]), "+f"(c[1]), "+f"(c[2]), "+f"(c[3])
        : "r"(a[0]), "r"(a[1]), "r"(a[2]), "r"(a[3]), "r"(b0), "r"(b1));
}
#define CP_ASYNC16(dst, src) \
    asm volatile("cp.async.cg.shared.global [%0], [%1], 16;" :: "r"(dst), "l"(src))
#define CP_COMMIT() asm volatile("cp.async.commit_group;" ::: "memory")
#define CP_WAIT0()  asm volatile("cp.async.wait_group 0;" ::: "memory")
#define CP_WAIT1()  asm volatile("cp.async.wait_group 1;" ::: "memory")

__device__ __forceinline__ void split4h(float4 v, uint2& hi, uint2& lo) {
    __half hx = __float2half(v.x), hy = __float2half(v.y);
    __half hz = __float2half(v.z), hw = __float2half(v.w);
    __half lx = __float2half(v.x - __half2float(hx));
    __half ly = __float2half(v.y - __half2float(hy));
    __half lz = __float2half(v.z - __half2float(hz));
    __half lw = __float2half(v.w - __half2float(hw));
    __half2 h01 = __halves2half2(hx, hy), h23 = __halves2half2(hz, hw);
    __half2 l01 = __halves2half2(lx, ly), l23 = __halves2half2(lz, lw);
    hi = make_uint2(*(uint32_t*)&h01, *(uint32_t*)&h23);
    lo = make_uint2(*(uint32_t*)&l01, *(uint32_t*)&l23);
}

__global__ void __launch_bounds__(256) split_kernel(
    const float4* __restrict__ src, uint2* __restrict__ hi,
    uint2* __restrict__ lo, int n4)
{
    int i = blockIdx.x * blockDim.x + threadIdx.x;
    if (i >= n4) return;
    uint2 h, l;
    split4h(src[i], h, l);
    hi[i] = h; lo[i] = l;
}
__global__ void __launch_bounds__(256) convert_kernel(
    const float4* __restrict__ src, uint2* __restrict__ hi, int n4)
{
    int i = blockIdx.x * blockDim.x + threadIdx.x;
    if (i >= n4) return;
    float4 v = src[i];
    __half2 h01 = __halves2half2(__float2half(v.x), __float2half(v.y));
    __half2 h23 = __halves2half2(__float2half(v.z), __float2half(v.w));
    hi[i] = make_uint2(*(uint32_t*)&h01, *(uint32_t*)&h23);
}

// ===========================================================================
// fp16 HMMA GEMM, 2-pass (A hi/lo, B single), 3-stage cp.async pipeline.
// Hi/lo MMA sweeps are separated so accumulator RAW pairs sit 16 independent
// MMAs apart (HMMA latency hidden despite asm-volatile ordering).
// ===========================================================================
#define BM 128
#define BN 128
#define BK 32
#define SROW 40
#define TILE_B (BM * SROW * 2)
#define STAGE_B (3 * TILE_B)
#define NSTAGE 3
#define GEMM_SMEM (NSTAGE * STAGE_B)

__global__ void __launch_bounds__(256) gemm_f16(
    const __half* __restrict__ Ah, const __half* __restrict__ Al,
    const __half* __restrict__ Bh,
    float* __restrict__ C, float* __restrict__ C2,
    int M, int N, int K, int ld)
{
    extern __shared__ char smem[];
    const uint32_t sbase = smem_u32(smem);

    const int tid  = threadIdx.x;
    const int wid  = tid >> 5;
    const int lane = tid & 31;
    const int bm = blockIdx.y * BM;
    const int bn = blockIdx.x * BN;
    const int zk = blockIdx.z * K;
    float* Co = blockIdx.z ? C2 : C;

    const int wm = (wid & 3) * 32;
    const int wn = (wid >> 2) * 64;

    float acc[2][8][4];
#pragma unroll
    for (int i = 0; i < 2; ++i)
#pragma unroll
        for (int j = 0; j < 8; ++j)
#pragma unroll
            for (int k = 0; k < 4; ++k) acc[i][j][k] = 0.f;

    const int aRow = lane & 15;
    const int aKof = (lane >> 4) << 3;

    const __half* srcs[3] = {Ah, Al, Bh};
    const int nch = K / BK;

    auto load_stage = [&](int stage, int k0) {
#pragma unroll
        for (int p = 0; p < 6; ++p) {
            int chunk = p * 256 + tid;
            int tile  = chunk >> 9;
            int idx   = chunk & 511;
            int row   = idx >> 2;
            int part  = idx & 3;
            int grow  = (tile < 2 ? bm : bn) + row;
            const __half* src = srcs[tile] + (size_t)grow * ld + zk + k0 + part * 8;
            uint32_t dst = sbase + stage * STAGE_B + tile * TILE_B
                         + row * (SROW * 2) + part * 16;
            CP_ASYNC16(dst, src);
        }
        CP_COMMIT();
    };

    load_stage(0, 0);
    if (nch > 1) load_stage(1, BK);

    for (int ch = 0; ch < nch; ++ch) {
        if (ch + 1 < nch) { CP_WAIT1(); } else { CP_WAIT0(); }
        __syncthreads();
        if (ch + 2 < nch) load_stage((ch + 2) % NSTAGE, (ch + 2) * BK);

        const uint32_t base = sbase + (ch % NSTAGE) * STAGE_B;
        const uint32_t uAh = base;
        const uint32_t uAl = base + TILE_B;
        const uint32_t uBh = base + 2 * TILE_B;

#pragma unroll
        for (int ks = 0; ks < 2; ++ks) {
            const int kb = ks * 16;
            // ---- load ALL fragments first ----
            uint32_t Afh[2][4], Afl[2][4], Bf[4][4];
#pragma unroll
            for (int mt = 0; mt < 2; ++mt) {
                uint32_t off = (uint32_t)((wm + mt * 16 + aRow) * SROW + kb + aKof) * 2;
                ldsm_x4(Afh[mt][0], Afh[mt][1], Afh[mt][2], Afh[mt][3], uAh + off);
                ldsm_x4(Afl[mt][0], Afl[mt][1], Afl[mt][2], Afl[mt][3], uAl + off);
            }
#pragma unroll
            for (int nt2 = 0; nt2 < 4; ++nt2) {
                uint32_t off = (uint32_t)((wn + nt2 * 16 + aRow) * SROW + kb + aKof) * 2;
                ldsm_x4(Bf[nt2][0], Bf[nt2][1], Bf[nt2][2], Bf[nt2][3], uBh + off);
            }
            // ---- hi sweep: 16 MMAs, all-distinct accumulators ----
#pragma unroll
            for (int nt2 = 0; nt2 < 4; ++nt2)
#pragma unroll
                for (int mt = 0; mt < 2; ++mt) {
                    mma_f16(acc[mt][nt2 * 2],     Afh[mt], Bf[nt2][0], Bf[nt2][2]);
                    mma_f16(acc[mt][nt2 * 2 + 1], Afh[mt], Bf[nt2][1], Bf[nt2][3]);
                }
            // ---- lo sweep: dependent re-writes now 16 MMAs downstream ----
#pragma unroll
            for (int nt2 = 0; nt2 < 4; ++nt2)
#pragma unroll
                for (int mt = 0; mt < 2; ++mt) {
                    mma_f16(acc[mt][nt2 * 2],     Afl[mt], Bf[nt2][0], Bf[nt2][2]);
                    mma_f16(acc[mt][nt2 * 2 + 1], Afl[mt], Bf[nt2][1], Bf[nt2][3]);
                }
        }
        __syncthreads();
    }

    const int g  = lane >> 2;
    const int cc = (lane & 3) * 2;
#pragma unroll
    for (int mt = 0; mt < 2; ++mt) {
#pragma unroll
        for (int nt = 0; nt < 8; ++nt) {
            int row0 = bm + wm + mt * 16 + g;
            int col  = bn + wn + nt * 8 + cc;
            *reinterpret_cast<float2*>(Co + (size_t)row0 * N + col) =
                make_float2(acc[mt][nt][0], acc[mt][nt][1]);
            *reinterpret_cast<float2*>(Co + (size_t)(row0 + 8) * N + col) =
                make_float2(acc[mt][nt][2], acc[mt][nt][3]);
        }
    }
}

// ---------------------------------------------------------------------------
// Depthwise causal conv (k=4) + bias + silu over u = xz[:, :, 0:DI]
// ---------------------------------------------------------------------------
__global__ void __launch_bounds__(256) conv_silu_kernel(
    const float* __restrict__ conv_w, const float* __restrict__ conv_b)
{
    int idx = blockIdx.x * blockDim.x + threadIdx.x;
    if (idx >= MROWS * DI) return;
    int d = idx % DI;
    int l = (idx / DI) % LL;
    int b = idx / (DI * LL);

    float acc = conv_b[d];
#pragma unroll
    for (int j = 0; j < 4; ++j) {
        int ll = l - 3 + j;
        if (ll >= 0)
            acc = fmaf(conv_w[d * 4 + j],
                       g_xz[(size_t)(b * LL + ll) * (2 * DI) + d], acc);
    }
    g_u[idx] = acc / (1.f + __expf(-acc));
}

// ---------------------------------------------------------------------------
// x_proj split-K partials + reduce
// ---------------------------------------------------------------------------
__global__ void __launch_bounds__(256) gemm_xproj_part(
    const float* __restrict__ W)
{
    __shared__ float As[32][33];
    __shared__ float Ws[32][81];

    const int tid = threadIdx.x;
    const int m0 = blockIdx.x * 32;
    const int kbase = blockIdx.y * (DI / 4);
    const int tx = tid & 15;
    const int ty = tid >> 4;

    float acc[2][5] = {};

    for (int kc = 0; kc < DI / 4; kc += 32) {
        int k0 = kbase + kc;
        for (int i = tid; i < 32 * 32; i += 256) {
            int m = i >> 5, k = i & 31;
            As[k][m] = g_u[(size_t)(m0 + m) * DI + k0 + k];
        }
        for (int i = tid; i < 80 * 32; i += 256) {
            int nn = i >> 5, k = i & 31;
            Ws[k][nn] = W[(size_t)nn * DI + k0 + k];
        }
        __syncthreads();
#pragma unroll
        for (int k = 0; k < 32; ++k) {
            float a0 = As[k][ty * 2];
            float a1 = As[k][ty * 2 + 1];
#pragma unroll
            for (int j = 0; j < 5; ++j) {
                float w = Ws[k][tx * 5 + j];
                acc[0][j] = fmaf(a0, w, acc[0][j]);
                acc[1][j] = fmaf(a1, w, acc[1][j]);
            }
        }
        __syncthreads();
    }
    float* dst = g_xp + (size_t)blockIdx.y * MROWS * XP;
#pragma unroll
    for (int i = 0; i < 2; ++i)
#pragma unroll
        for (int j = 0; j < 5; ++j)
            dst[(size_t)(m0 + ty * 2 + i) * XP + tx * 5 + j] = acc[i][j];
}

__global__ void __launch_bounds__(256) xproj_reduce(int n4)
{
    int i = blockIdx.x * blockDim.x + threadIdx.x;
    if (i >= n4) return;
    const float4* p = (const float4*)g_xp;
    const int S = MROWS * XP / 4;
    float4 a = p[i], b = p[i + S], c = p[i + 2 * S], d = p[i + 3 * S];
    ((float4*)g_xdbl)[i] = make_float4(a.x + b.x + c.x + d.x, a.y + b.y + c.y + d.y,
                                       a.z + b.z + c.z + d.z, a.w + b.w + c.w + d.w);
}

// ---------------------------------------------------------------------------
// dt_proj (K=48) + bias + softplus. 64 m x 128 d per block.
// ---------------------------------------------------------------------------
__global__ void __launch_bounds__(256) dtproj_softplus(
    const float* __restrict__ W, const float* __restrict__ bias)
{
    __shared__ __align__(16) float Ls[RK][68];
    __shared__ __align__(16) float Ws[RK][132];

    const int tid = threadIdx.x;
    const int m0 = blockIdx.x * 64;
    const int d0 = blockIdx.y * 128;

    for (int i = tid; i < 64 * RK; i += 256) {
        int m = i / RK, r = i - m * RK;
        Ls[r][m] = g_xdbl[(size_t)(m0 + m) * XP + r];
    }
    for (int i = tid; i < 128 * RK; i += 256) {
        int d = i / RK, r = i - d * RK;
        Ws[r][d] = W[(size_t)(d0 + d) * RK + r];
    }
    __syncthreads();

    const int tx = tid & 15;
    const int ty = tid >> 4;
    float acc[4][8] = {};
#pragma unroll
    for (int r = 0; r < RK; ++r) {
        float4 a  = *reinterpret_cast<const float4*>(&Ls[r][ty * 4]);
        float4 w0 = *reinterpret_cast<const float4*>(&Ws[r][tx * 8]);
        float4 w1 = *reinterpret_cast<const float4*>(&Ws[r][tx * 8 + 4]);
        const float av[4] = {a.x, a.y, a.z, a.w};
        const float wv[8] = {w0.x, w0.y, w0.z, w0.w, w1.x, w1.y, w1.z, w1.w};
#pragma unroll
        for (int i = 0; i < 4; ++i)
#pragma unroll
            for (int j = 0; j < 8; ++j)
                acc[i][j] = fmaf(av[i], wv[j], acc[i][j]);
    }
    float bv[8];
#pragma unroll
    for (int j = 0; j < 8; ++j) bv[j] = bias[d0 + tx * 8 + j];
#pragma unroll
    for (int i = 0; i < 4; ++i) {
        float o[8];
#pragma unroll
        for (int j = 0; j < 8; ++j) {
            float v = acc[i][j] + bv[j];
            o[j] = (v > 20.f) ? v : __logf(1.f + __expf(v));
        }
        float* dst = &g_dt[(size_t)(m0 + ty * 4 + i) * DI + d0 + tx * 8];
        *reinterpret_cast<float4*>(dst)     = make_float4(o[0], o[1], o[2], o[3]);
        *reinterpret_cast<float4*>(dst + 4) = make_float4(o[4], o[5], o[6], o[7]);
    }
}

// ---------------------------------------------------------------------------
// Segmented selective scan. 128 threads = 8 d x 16 n; grid = BB*SEG*192.
// ---------------------------------------------------------------------------
#define SCAN_T 32
#define SCAN_D 8
#define DGRPS (DI / SCAN_D)   // 192

__global__ void __launch_bounds__(128) scan_pass1(const float* __restrict__ A_log)
{
    int t0 = blockIdx.x;
    const int dgrp = t0 % DGRPS; t0 /= DGRPS;
    const int s = t0 % SEG;
    const int b = t0 / SEG;
    const int d0 = dgrp * SCAN_D;
    const int tid  = threadIdx.x;
    const int lane = tid & 31;
    const int warp = tid >> 5;
    const int n    = lane & 15;
    const int dloc = (warp << 1) | (lane >> 4);
    const int d    = d0 + dloc;

    const float a = -__expf(A_log[d * NS + n]);

    __shared__ float dt_s[SCAN_T][SCAN_D];
    __shared__ float u_s [SCAN_T][SCAN_D];
    __shared__ float B_s [SCAN_T][16];

    float h = 0.f, cum = 1.f;

    for (int l0 = s * SLEN; l0 < (s + 1) * SLEN; l0 += SCAN_T) {
        for (int i = tid; i < SCAN_T * SCAN_D; i += 128) {
            int tt = i >> 3, dd = i & 7;
            size_t row = (size_t)(b * LL + l0 + tt);
            dt_s[tt][dd] = g_dt[row * DI + d0 + dd];
            u_s [tt][dd] = g_u [row * DI + d0 + dd];
        }
        for (int i = tid; i < SCAN_T * 16; i += 128) {
            int tt = i >> 4, nn = i & 15;
            B_s[tt][nn] = g_xdbl[(size_t)(b * LL + l0 + tt) * XP + RK + nn];
        }
        __syncthreads();
#pragma unroll 8
        for (int t = 0; t < SCAN_T; ++t) {
            float dtv = dt_s[t][dloc];
            float e = __expf(dtv * a);
            h = fmaf(h, e, dtv * u_s[t][dloc] * B_s[t][n]);
            cum *= e;
        }
        __syncthreads();
    }
    size_t off = ((size_t)(b * SEG + s) * DI + d) * NS + n;
    g_hend[off] = h;
    g_pend[off] = cum;
}

__global__ void __launch_bounds__(256) scan_mid()
{
    int i = blockIdx.x * blockDim.x + threadIdx.x;
    if (i >= BB * DI * NS) return;
    int n = i & (NS - 1);
    int d = (i / NS) % DI;
    int b = i / (NS * DI);
    float h = 0.f;
#pragma unroll
    for (int s = 0; s < SEG; ++s) {
        size_t off = ((size_t)(b * SEG + s) * DI + d) * NS + n;
        g_hin[off] = h;
        h = fmaf(g_pend[off], h, g_hend[off]);
    }
}

__global__ void __launch_bounds__(128) scan_pass3(
    const float* __restrict__ A_log, const float* __restrict__ Dvec)
{
    int t0 = blockIdx.x;
    const int dgrp = t0 % DGRPS; t0 /= DGRPS;
    const int s = t0 % SEG;
    const int b = t0 / SEG;
    const int d0 = dgrp * SCAN_D;
    const int tid  = threadIdx.x;
    const int lane = tid & 31;
    const int warp = tid >> 5;
    const int n    = lane & 15;
    const int dloc = (warp << 1) | (lane >> 4);
    const int d    = d0 + dloc;

    const float a = -__expf(A_log[d * NS + n]);

    __shared__ float dt_s[SCAN_T][SCAN_D];
    __shared__ float u_s [SCAN_T][SCAN_D];
    __shared__ float z_s [SCAN_T][SCAN_D];
    __shared__ float B_s [SCAN_T][16];
    __shared__ float C_s [SCAN_T][16];
    __shared__ float yb  [SCAN_T][SCAN_D];

    float h = g_hin[((size_t)(b * SEG + s) * DI + d) * NS + n];

    for (int l0 = s * SLEN; l0 < (s + 1) * SLEN; l0 += SCAN_T) {
        for (int i = tid; i < SCAN_T * SCAN_D; i += 128) {
            int tt = i >> 3, dd = i & 7;
            size_t row = (size_t)(b * LL + l0 + tt);
            dt_s[tt][dd] = g_dt[row * DI + d0 + dd];
            u_s [tt][dd] = g_u [row * DI + d0 + dd];
            z_s [tt][dd] = g_xz[row * (2 * DI) + DI + d0 + dd];
        }
        for (int i = tid; i < SCAN_T * 16; i += 128) {
            int tt = i >> 4, nn = i & 15;
            size_t row = (size_t)(b * LL + l0 + tt);
            B_s[tt][nn] = g_xdbl[row * XP + RK + nn];
            C_s[tt][nn] = g_xdbl[row * XP + RK + NS + nn];
        }
        __syncthreads();

#pragma unroll 8
        for (int t = 0; t < SCAN_T; ++t) {
            float dtv = dt_s[t][dloc];
            h = fmaf(h, __expf(dtv * a), dtv * u_s[t][dloc] * B_s[t][n]);
            float p = h * C_s[t][n];
            p += __shfl_xor_sync(0xffffffffu, p, 8);
            p += __shfl_xor_sync(0xffffffffu, p, 4);
            p += __shfl_xor_sync(0xffffffffu, p, 2);
            p += __shfl_xor_sync(0xffffffffu, p, 1);
            if (n == 0) yb[t][dloc] = p;
        }
        __syncthreads();

        for (int i = tid; i < SCAN_T * SCAN_D; i += 128) {
            int tt = i >> 3, dd = i & 7;
            size_t row = (size_t)(b * LL + l0 + tt);
            float zz = z_s[tt][dd];
            float sz = zz / (1.f + __expf(-zz));
            float yv = fmaf(u_s[tt][dd], Dvec[d0 + dd], yb[tt][dd]) * sz;
            __half hv = __float2half(yv);
            __half lv = __float2half(yv - __half2float(hv));
            g_ah[row * DI + d0 + dd] = hv;
            g_al[row * DI + d0 + dd] = lv;
        }
        __syncthreads();
    }
}

// ---------------------------------------------------------------------------
// residual + LayerNorm over DM=768 (sums both out_proj partials)
// ---------------------------------------------------------------------------
__global__ void __launch_bounds__(256) resid_ln(
    const float* __restrict__ x, const float* __restrict__ w,
    const float* __restrict__ bln, float* __restrict__ out)
{
    const int row = blockIdx.x;
    const float* o1 = g_ob  + (size_t)row * DM;
    const float* o2 = g_ob2 + (size_t)row * DM;
    const float* xr = x     + (size_t)row * DM;

    float v[3];
    float s = 0.f, ss = 0.f;
#pragma unroll
    for (int i = 0; i < 3; ++i) {
        int c = threadIdx.x + i * 256;
        v[i] = o1[c] + o2[c] + xr[c];
        s += v[i];
        ss += v[i] * v[i];
    }
#pragma unroll
    for (int off = 16; off; off >>= 1) {
        s  += __shfl_xor_sync(0xffffffffu, s,  off);
        ss += __shfl_xor_sync(0xffffffffu, ss, off);
    }
    __shared__ float sbuf[16];
    int warp = threadIdx.x >> 5, lane = threadIdx.x & 31;
    if (lane == 0) { sbuf[warp] = s; sbuf[8 + warp] = ss; }
    __syncthreads();
    float S = 0.f, SS = 0.f;
#pragma unroll
    for (int i = 0; i < 8; ++i) { S += sbuf[i]; SS += sbuf[8 + i]; }
    float mean = S * (1.f / DM);
    float var  = SS * (1.f / DM) - mean * mean;
    float rstd = rsqrtf(var + 1e-5f);
#pragma unroll
    for (int i = 0; i < 3; ++i) {
        int c = threadIdx.x + i * 256;
        out[(size_t)row * DM + c] = (v[i] - mean) * rstd * w[c] + bln[c];
    }
}

// ---------------------------------------------------------------------------
extern "C" void kernel_launch(void* const* d_in, const int* in_sizes, int n_in,
                              void* d_out, int out_size)
{
    const float* x       = (const float*)d_in[0];
    const float* in_w    = (const float*)d_in[1];
    const float* conv_w  = (const float*)d_in[2];
    const float* conv_b  = (const float*)d_in[3];
    const float* xproj_w = (const float*)d_in[4];
    const float* dt_w    = (const float*)d_in[5];
    const float* dt_b    = (const float*)d_in[6];
    const float* A_log   = (const float*)d_in[7];
    const float* Dv      = (const float*)d_in[8];
    const float* out_w   = (const float*)d_in[9];
    const float* ln_w    = (const float*)d_in[10];
    const float* ln_b    = (const float*)d_in[11];
    float* out = (float*)d_out;

    float *p_xz, *p_ob, *p_ob2;
    cudaGetSymbolAddress((void**)&p_xz,  g_xz);
    cudaGetSymbolAddress((void**)&p_ob,  g_ob);
    cudaGetSymbolAddress((void**)&p_ob2, g_ob2);
    __half *p_ah, *p_al, *p_bh, *p_bh2;
    cudaGetSymbolAddress((void**)&p_ah,  g_ah);
    cudaGetSymbolAddress((void**)&p_al,  g_al);
    cudaGetSymbolAddress((void**)&p_bh,  g_bh);
    cudaGetSymbolAddress((void**)&p_bh2, g_bh2);

    cudaFuncSetAttribute(gemm_f16, cudaFuncAttributeMaxDynamicSharedMemorySize,
                         GEMM_SMEM);

    // (1) split x -> A hi/lo
    {
        int n4 = MROWS * DM / 4;
        split_kernel<<<(n4 + 255) / 256, 256>>>(
            (const float4*)x, (uint2*)p_ah, (uint2*)p_al, n4);
    }
    // (2) convert in_proj_w
    {
        int n4 = 2 * DI * DM / 4;
        convert_kernel<<<(n4 + 255) / 256, 256>>>(
            (const float4*)in_w, (uint2*)p_bh, n4);
    }
    // (3) convert out_proj_w
    {
        int n4 = DM * DI / 4;
        convert_kernel<<<(n4 + 255) / 256, 256>>>(
            (const float4*)out_w, (uint2*)p_bh2, n4);
    }

    // (4) in_proj GEMM: [4096, 3072]
    gemm_f16<<<dim3((2 * DI) / BN, MROWS / BM, 1), 256, GEMM_SMEM>>>(
        p_ah, p_al, p_bh, p_xz, p_xz, MROWS, 2 * DI, DM, DM);

    // (5) conv + silu
    conv_silu_kernel<<<(MROWS * DI + 255) / 256, 256>>>(conv_w, conv_b);

    // (6,7) x_proj
    gemm_xproj_part<<<dim3(MROWS / 32, 4), 256>>>(xproj_w);
    {
        int n4 = MROWS * XP / 4;
        xproj_reduce<<<(n4 + 255) / 256, 256>>>(n4);
    }

    // (8) dt_proj
    dtproj_softplus<<<dim3(MROWS / 64, DI / 128), 256>>>(dt_w, dt_b);

    // (9) segmented scan
    scan_pass1<<<BB * SEG * DGRPS, 128>>>(A_log);
    scan_mid<<<(BB * DI * NS + 255) / 256, 256>>>();
    scan_pass3<<<BB * SEG * DGRPS, 128>>>(A_log, Dv);

    // (10) out_proj GEMM split-K x2: [4096, 768], K=768 per half
    gemm_f16<<<dim3(DM / BN, MROWS / BM, 2), 256, GEMM_SMEM>>>(
        p_ah, p_al, p_bh2, p_ob, p_ob2, MROWS, DM, DI / 2, DI);

    // (11) residual + LayerNorm
    resid_ln<<<MROWS, 256>>>(x, ln_w, ln_b, out);
}